// round 9
// baseline (speedup 1.0000x reference)
#include <cuda_runtime.h>
#include <cstdint>

// ---------------------------------------------------------------------------
// L2Attention via tf32 mma.sync (m16n8k8).
// Attention: 2-stage 64-key ring pipeline (loads overlap compute),
// softmax pipelined between score and PV MMAs.
// b=4, n=1024, dim=1024, heads=16, d=64
// ---------------------------------------------------------------------------

#define M_ROWS 4096
#define DIM    1024

__device__ float g_q[M_ROWS * DIM];
__device__ float g_v[M_ROWS * DIM];
__device__ float g_a[M_ROWS * DIM];
__device__ float g_x[M_ROWS * DIM];
__device__ float g_wq[DIM * DIM];
__device__ float g_wv[DIM * DIM];
__device__ float g_wo[DIM * DIM];
__device__ float g_sq[64 * 1024];     // |q|^2 * 0.125 * log2(e) per (b,h,n)

#define C2EXP 0.36067376022224085f    // 2 * 0.125 * log2(e)

__device__ __forceinline__ float tf32r(float x) {
    uint32_t u;
    asm("cvt.rna.tf32.f32 %0, %1;" : "=r"(u) : "f"(x));
    return __uint_as_float(u);
}
__device__ __forceinline__ float ex2(float x) {
    float r;
    asm("ex2.approx.f32 %0, %1;" : "=f"(r) : "f"(x));
    return r;
}

__device__ __forceinline__ void mma_tf32(float c[4],
                                         uint32_t a0, uint32_t a1,
                                         uint32_t a2, uint32_t a3,
                                         uint32_t b0, uint32_t b1) {
    asm volatile(
        "mma.sync.aligned.m16n8k8.row.col.f32.tf32.tf32.f32 "
        "{%0,%1,%2,%3}, {%4,%5,%6,%7}, {%8,%9}, {%0,%1,%2,%3};\n"
        : "+f"(c[0]), "+f"(c[1]), "+f"(c[2]), "+f"(c[3])
        : "r"(a0), "r"(a1), "r"(a2), "r"(a3), "r"(b0), "r"(b1));
}

__device__ __forceinline__ void cp16(uint32_t smem_u32, const float* gptr) {
    asm volatile("cp.async.cg.shared.global [%0], [%1], 16;\n"
                 :: "r"(smem_u32), "l"(gptr));
}
#define CP_COMMIT() asm volatile("cp.async.commit_group;\n" ::: "memory")

// ---------------------------------------------------------------------------
// one launch: round x + Wq + Wv + Wo to tf32 (RNA)
// ---------------------------------------------------------------------------
__global__ __launch_bounds__(256) void round_all_kernel(
    const float4* __restrict__ x,  float4* __restrict__ xo,
    const float4* __restrict__ w0, float4* __restrict__ w0o,
    const float4* __restrict__ w1, float4* __restrict__ w1o,
    const float4* __restrict__ w2, float4* __restrict__ w2o)
{
    int i = blockIdx.x * 256 + threadIdx.x;
    {
        float4 v = x[i];
        v.x = tf32r(v.x); v.y = tf32r(v.y);
        v.z = tf32r(v.z); v.w = tf32r(v.w);
        xo[i] = v;
    }
    if (i < 262144) {
        float4 a = w0[i], b = w1[i], c = w2[i];
        a.x = tf32r(a.x); a.y = tf32r(a.y); a.z = tf32r(a.z); a.w = tf32r(a.w);
        b.x = tf32r(b.x); b.y = tf32r(b.y); b.z = tf32r(b.z); b.w = tf32r(b.w);
        c.x = tf32r(c.x); c.y = tf32r(c.y); c.z = tf32r(c.z); c.w = tf32r(c.w);
        w0o[i] = a; w1o[i] = b; w2o[i] = c;
    }
}

// ---------------------------------------------------------------------------
// scaled |q|^2 table: sqg[(b*16+h)*1024+n] = |q_bhn|^2 * 0.125 * log2(e)
// ---------------------------------------------------------------------------
__global__ __launch_bounds__(256) void sq_kernel(
    const float* __restrict__ q, float* __restrict__ sqg)
{
    int o  = blockIdx.x * 256 + threadIdx.x;
    int n  = o & 1023;
    int bh = o >> 10;
    int b  = bh >> 4, h = bh & 15;
    const float4* p = (const float4*)(q + ((size_t)(b * 1024 + n)) * DIM + h * 64);
    float s = 0.f;
#pragma unroll
    for (int i = 0; i < 16; i++) {
        float4 v = p[i];
        s += v.x * v.x + v.y * v.y + v.z * v.z + v.w * v.w;
    }
    sqg[o] = s * (0.5f * C2EXP);
}

// ---------------------------------------------------------------------------
// GEMM (unchanged): 256 thr, 8 warps (4M x 2N), tile 128x128, K-step 32,
// 2-stage cp.async. blockIdx.z selects output -> fused Q/V projection.
// ---------------------------------------------------------------------------
#define GS 36
#define G_STAGE (2 * 128 * GS)
#define GEMM_SMEM (2 * G_STAGE * 4)

__device__ __forceinline__ void g_load(
    uint32_t sb, int st, const float* __restrict__ A,
    const float* __restrict__ B, int bm, int bn, int K, int k0, int t)
{
    uint32_t ab = sb + st * G_STAGE * 4;
    uint32_t bb = ab + 128 * GS * 4;
#pragma unroll
    for (int l = 0; l < 4; l++) {
        int idx = t + l * 256;
        int r = idx >> 3, c4 = (idx & 7) * 4;
        cp16(ab + (r * GS + c4) * 4, A + (size_t)(bm + r) * K + k0 + c4);
    }
#pragma unroll
    for (int l = 0; l < 4; l++) {
        int idx = t + l * 256;
        int r = idx >> 3, c4 = (idx & 7) * 4;
        cp16(bb + (r * GS + c4) * 4, B + (size_t)(bn + r) * K + k0 + c4);
    }
    CP_COMMIT();
}

__global__ __launch_bounds__(256, 2) void gemm_tf32_kernel(
    const float* __restrict__ A,
    const float* __restrict__ B0, const float* __restrict__ bias0,
    float* __restrict__ C0,
    const float* __restrict__ B1, const float* __restrict__ bias1,
    float* __restrict__ C1,
    int N, int K, int rnd)
{
    extern __shared__ float sm[];
    const uint32_t sb = (uint32_t)__cvta_generic_to_shared(sm);

    const float* B    = blockIdx.z ? B1 : B0;
    const float* bias = blockIdx.z ? bias1 : bias0;
    float*       C    = blockIdx.z ? C1 : C0;

    const int t    = threadIdx.x;
    const int w    = t >> 5;
    const int lane = t & 31;
    const int g    = lane >> 2;
    const int tq   = lane & 3;
    const int wm   = w & 3;
    const int wn   = w >> 2;
    const int bm   = blockIdx.y * 128;
    const int bn   = blockIdx.x * 128;

    float acc[2][8][4];
#pragma unroll
    for (int i = 0; i < 2; i++)
#pragma unroll
        for (int j = 0; j < 8; j++)
#pragma unroll
            for (int r = 0; r < 4; r++) acc[i][j][r] = 0.f;

    g_load(sb, 0, A, B, bm, bn, K, 0, t);

    for (int k0 = 0; k0 < K; k0 += 32) {
        const int cur = (k0 >> 5) & 1;
        asm volatile("cp.async.wait_group 0;\n" ::: "memory");
        __syncthreads();
        if (k0 + 32 < K)
            g_load(sb, cur ^ 1, A, B, bm, bn, K, k0 + 32, t);

        const float* As = sm + cur * G_STAGE;
        const float* Bs = As + 128 * GS;

#pragma unroll
        for (int ks = 0; ks < 4; ks++) {
            const int kk = ks * 8;
            uint32_t a[2][4], b[8][2];
#pragma unroll
            for (int i = 0; i < 2; i++) {
                const float* ar = As + (wm * 32 + i * 16 + g) * GS + kk + tq;
                a[i][0] = __float_as_uint(ar[0]);
                a[i][1] = __float_as_uint(ar[8 * GS]);
                a[i][2] = __float_as_uint(ar[4]);
                a[i][3] = __float_as_uint(ar[8 * GS + 4]);
            }
#pragma unroll
            for (int j = 0; j < 8; j++) {
                const float* br = Bs + (wn * 64 + j * 8 + g) * GS + kk + tq;
                b[j][0] = __float_as_uint(br[0]);
                b[j][1] = __float_as_uint(br[4]);
            }
#pragma unroll
            for (int i = 0; i < 2; i++)
#pragma unroll
                for (int j = 0; j < 8; j++)
                    mma_tf32(acc[i][j], a[i][0], a[i][1], a[i][2], a[i][3],
                             b[j][0], b[j][1]);
        }
    }

#pragma unroll
    for (int i = 0; i < 2; i++) {
        int row0 = bm + wm * 32 + i * 16 + g;
#pragma unroll
        for (int j = 0; j < 8; j++) {
            int col0 = bn + wn * 64 + j * 8 + 2 * tq;
            float b0 = bias[col0], b1 = bias[col0 + 1];
            float v00 = acc[i][j][0] + b0, v01 = acc[i][j][1] + b1;
            float v10 = acc[i][j][2] + b0, v11 = acc[i][j][3] + b1;
            if (rnd) { v00 = tf32r(v00); v01 = tf32r(v01);
                       v10 = tf32r(v10); v11 = tf32r(v11); }
            *(float2*)(C + (size_t)row0 * N + col0)       = make_float2(v00, v01);
            *(float2*)(C + (size_t)(row0 + 8) * N + col0) = make_float2(v10, v11);
        }
    }
}

// ---------------------------------------------------------------------------
// Fused attention: 128-query tile, 8 warps x 16 rows, 2 CTAs/SM.
// K/V streamed as 16 tiles of 64 keys through a 2-stage cp.async ring:
// tile i+2's load issues after tile i's buffers free, completes during
// tile i+1's compute -> global latency fully hidden.
// p = exp2(qk*C2 - si' - sj');   scores <= ~0 -> softmax w/o running max.
// ---------------------------------------------------------------------------
#define SWS 68
#define VSd 72
#define KST (64 * SWS)              // 4352 floats per K stage
#define VST (64 * VSd)              // 4608 floats per V stage
#define OFF_K  0                    // 2 stages: 8704
#define OFF_V  (2 * KST)            // 2 stages: 9216
#define OFF_S  (OFF_V + 2 * VST)    // 8704 (S chunks; Q staging in prologue)
#define OFF_SQ (OFF_S + 8704)       // 1024
#define ATT_FL (OFF_SQ + 1024)      // 27648 floats = 110592 B

// stage one 64-key tile (K + V) into ring stage s
__device__ __forceinline__ void a_load(
    uint32_t sb, int s, const float* __restrict__ qb,
    const float* __restrict__ vb, int key0, int t)
{
#pragma unroll
    for (int l = 0; l < 4; l++) {
        int idx = t + l * 256;                // 0..1023
        int r = idx >> 4, c4 = (idx & 15) * 4;
        cp16(sb + (OFF_K + s * KST + r * SWS + c4) * 4,
             qb + (size_t)(key0 + r) * DIM + c4);
        cp16(sb + (OFF_V + s * VST + r * VSd + c4) * 4,
             vb + (size_t)(key0 + r) * DIM + c4);
    }
    CP_COMMIT();
}

__global__ __launch_bounds__(256, 2) void attn_tf32_kernel(
    const float* __restrict__ q, const float* __restrict__ v,
    const float* __restrict__ sqg, float* __restrict__ o)
{
    extern __shared__ float sm[];
    const uint32_t sb = (uint32_t)__cvta_generic_to_shared(sm);

    const int bh = blockIdx.y;
    const int b  = bh >> 4;
    const int h  = bh & 15;
    const int qt = blockIdx.x * 128;
    const int t    = threadIdx.x;
    const int w    = t >> 5;
    const int lane = t & 31;
    const int g    = lane >> 2;
    const int tq   = lane & 3;
    const int i0   = 16 * w;

    const float* qbase = q + (size_t)b * 1024 * DIM + h * 64;
    const float* vbase = v + (size_t)b * 1024 * DIM + h * 64;

    // prefetch tiles 0 and 1 into the ring
    a_load(sb, 0, qbase, vbase, 0, t);
    a_load(sb, 1, qbase, vbase, 64, t);

    // scaled |q|^2 table for this (b,h)
    ((float4*)(sm + OFF_SQ))[t] = ((const float4*)(sqg + (size_t)bh * 1024))[t];

    // stage Q tile into S region (transient)
    float* Qs = sm + OFF_S;
#pragma unroll
    for (int l = 0; l < 8; l++) {
        int idx = t + l * 256;
        int r = idx >> 4, c4 = (idx & 15) * 4;
        *(float4*)(Qs + r * SWS + c4) =
            *(const float4*)(qbase + (size_t)(qt + r) * DIM + c4);
    }
    __syncthreads();

    uint32_t qa[8][4];
#pragma unroll
    for (int ks = 0; ks < 8; ks++) {
        const float* qr = Qs + (i0 + g) * SWS + ks * 8 + tq;
        qa[ks][0] = __float_as_uint(qr[0]);
        qa[ks][1] = __float_as_uint(qr[8 * SWS]);
        qa[ks][2] = __float_as_uint(qr[4]);
        qa[ks][3] = __float_as_uint(qr[8 * SWS + 4]);
    }
    const float* sqa = sm + OFF_SQ;
    const float si_lo = sqa[qt + i0 + g];
    const float si_hi = sqa[qt + i0 + 8 + g];
    __syncthreads();   // Q staging fully consumed -> S region reusable

    float oacc[8][4];
#pragma unroll
    for (int j = 0; j < 8; j++)
#pragma unroll
        for (int r = 0; r < 4; r++) oacc[j][r] = 0.f;
    float den_lo = 0.f, den_hi = 0.f;
    float* Swb = sm + OFF_S + w * (16 * SWS);

    for (int it = 0; it < 16; it++) {
        const int s = it & 1;
        // tile it's loads complete (tile it+1's group may stay in flight)
        if (it < 15)
            asm volatile("cp.async.wait_group 1;\n" ::: "memory");
        else
            asm volatile("cp.async.wait_group 0;\n" ::: "memory");
        __syncthreads();

        const float* Ksc = sm + OFF_K + s * KST;
        const float* Vsc = sm + OFF_V + s * VST;
        const float* sqk = sqa + it * 64;

        float c[4][4];
        // ---- scores chunk 0 (keys 0..31 of tile) ----
#pragma unroll
        for (int jj = 0; jj < 4; jj++)
#pragma unroll
            for (int r = 0; r < 4; r++) c[jj][r] = 0.f;
#pragma unroll
        for (int ks = 0; ks < 8; ks++)
#pragma unroll
            for (int jj = 0; jj < 4; jj++) {
                const float* kr = Ksc + (jj * 8 + g) * SWS + ks * 8 + tq;
                mma_tf32(c[jj], qa[ks][0], qa[ks][1], qa[ks][2], qa[ks][3],
                         __float_as_uint(kr[0]), __float_as_uint(kr[4]));
            }

#pragma unroll
        for (int jc = 0; jc < 2; jc++) {
            const int par = jc * 32;

            // ---- softmax(jc) ----
#pragma unroll
            for (int jj = 0; jj < 4; jj++) {
                int cb = jj * 8 + 2 * tq;
                float sj0 = sqk[par + cb], sj1 = sqk[par + cb + 1];
                float e00 = tf32r(ex2(fmaf(c[jj][0], C2EXP, -si_lo - sj0)));
                float e01 = tf32r(ex2(fmaf(c[jj][1], C2EXP, -si_lo - sj1)));
                float e10 = tf32r(ex2(fmaf(c[jj][2], C2EXP, -si_hi - sj0)));
                float e11 = tf32r(ex2(fmaf(c[jj][3], C2EXP, -si_hi - sj1)));
                den_lo += e00 + e01;
                den_hi += e10 + e11;
                *(float2*)(Swb + g * SWS + par + cb)       = make_float2(e00, e01);
                *(float2*)(Swb + (g + 8) * SWS + par + cb) = make_float2(e10, e11);
            }
            __syncwarp();

            // ---- scores(jc+1): refill c while tensor pipe drains ----
            if (jc < 1) {
#pragma unroll
                for (int jj = 0; jj < 4; jj++)
#pragma unroll
                    for (int r = 0; r < 4; r++) c[jj][r] = 0.f;
#pragma unroll
                for (int ks = 0; ks < 8; ks++)
#pragma unroll
                    for (int jj = 0; jj < 4; jj++) {
                        const float* kr = Ksc + ((4 + jj) * 8 + g) * SWS + ks * 8 + tq;
                        mma_tf32(c[jj], qa[ks][0], qa[ks][1], qa[ks][2], qa[ks][3],
                                 __float_as_uint(kr[0]), __float_as_uint(kr[4]));
                    }
            }

            // ---- PV(jc) ----
#pragma unroll
            for (int ksl = 0; ksl < 4; ksl++) {
                const float* sr = Swb + g * SWS + par + ksl * 8 + tq;
                uint32_t a0 = __float_as_uint(sr[0]);
                uint32_t a1 = __float_as_uint(sr[8 * SWS]);
                uint32_t a2 = __float_as_uint(sr[4]);
                uint32_t a3 = __float_as_uint(sr[8 * SWS + 4]);
                const int vrow = par + ksl * 8 + tq;
#pragma unroll
                for (int j = 0; j < 8; j++) {
                    uint32_t b0 = __float_as_uint(Vsc[vrow * VSd + j * 8 + g]);
                    uint32_t b1 = __float_as_uint(Vsc[(vrow + 4) * VSd + j * 8 + g]);
                    mma_tf32(oacc[j], a0, a1, a2, a3, b0, b1);
                }
            }
        }
        __syncthreads();   // stage s fully consumed by all warps

        // refill stage s with tile it+2 (completes during tile it+1 compute)
        if (it + 2 < 16)
            a_load(sb, s, qbase, vbase, (it + 2) * 64, t);
    }

    den_lo += __shfl_xor_sync(0xffffffffu, den_lo, 1);
    den_lo += __shfl_xor_sync(0xffffffffu, den_lo, 2);
    den_hi += __shfl_xor_sync(0xffffffffu, den_hi, 1);
    den_hi += __shfl_xor_sync(0xffffffffu, den_hi, 2);
    const float inv_lo = 1.f / den_lo;
    const float inv_hi = 1.f / den_hi;

    float* orow_lo = o + (size_t)(b * 1024 + qt + i0 + g) * DIM + h * 64;
    float* orow_hi = o + (size_t)(b * 1024 + qt + i0 + 8 + g) * DIM + h * 64;
#pragma unroll
    for (int j = 0; j < 8; j++) {
        int col = j * 8 + 2 * tq;
        *(float2*)(orow_lo + col) = make_float2(tf32r(oacc[j][0] * inv_lo),
                                                tf32r(oacc[j][1] * inv_lo));
        *(float2*)(orow_hi + col) = make_float2(tf32r(oacc[j][2] * inv_hi),
                                                tf32r(oacc[j][3] * inv_hi));
    }
}

// ---------------------------------------------------------------------------
extern "C" void kernel_launch(void* const* d_in, const int* in_sizes, int n_in,
                              void* d_out, int out_size)
{
    const float* x  = (const float*)d_in[0];
    const float* Wq = (const float*)d_in[1];
    const float* bq = (const float*)d_in[2];
    const float* Wv = (const float*)d_in[3];
    const float* bv = (const float*)d_in[4];
    const float* Wo = (const float*)d_in[5];
    const float* bo = (const float*)d_in[6];
    float* out = (float*)d_out;

    float *qp, *vp, *ap, *xp, *wqp, *wvp, *wop, *sqp;
    cudaGetSymbolAddress((void**)&qp,  g_q);
    cudaGetSymbolAddress((void**)&vp,  g_v);
    cudaGetSymbolAddress((void**)&ap,  g_a);
    cudaGetSymbolAddress((void**)&xp,  g_x);
    cudaGetSymbolAddress((void**)&wqp, g_wq);
    cudaGetSymbolAddress((void**)&wvp, g_wv);
    cudaGetSymbolAddress((void**)&wop, g_wo);
    cudaGetSymbolAddress((void**)&sqp, g_sq);

    cudaFuncSetAttribute(gemm_tf32_kernel,
                         cudaFuncAttributeMaxDynamicSharedMemorySize, GEMM_SMEM);
    cudaFuncSetAttribute(attn_tf32_kernel,
                         cudaFuncAttributeMaxDynamicSharedMemorySize,
                         (int)(ATT_FL * sizeof(float)));

    round_all_kernel<<<4096, 256>>>(
        (const float4*)x,  (float4*)xp,
        (const float4*)Wq, (float4*)wqp,
        (const float4*)Wv, (float4*)wvp,
        (const float4*)Wo, (float4*)wop);

    gemm_tf32_kernel<<<dim3(8, 32, 2), 256, GEMM_SMEM>>>(
        xp, wqp, bq, qp, wvp, bv, vp, DIM, DIM, 1);

    sq_kernel<<<256, 256>>>(qp, sqp);

    attn_tf32_kernel<<<dim3(8, 64), 256, ATT_FL * sizeof(float)>>>(qp, vp, sqp, ap);

    gemm_tf32_kernel<<<dim3(8, 32, 1), 256, GEMM_SMEM>>>(
        ap, wop, bo, out, wop, bo, out, DIM, DIM, 0);
}

// round 10
// speedup vs baseline: 1.7862x; 1.7862x over previous
#include <cuda_runtime.h>
#include <cuda_fp16.h>
#include <cstdint>

// ---------------------------------------------------------------------------
// L2Attention via fp16 mma.sync (m16n8k16, fp32 accumulate).
// fp16 mantissa == tf32 mantissa (10 bits) -> same rounding error,
// 2x flops/instr and half the LDS bytes.
// b=4, n=1024, dim=1024, heads=16, d=64
// ---------------------------------------------------------------------------

#define M_ROWS 4096
#define DIM    1024

__device__ __half g_q [M_ROWS * DIM];
__device__ __half g_vt[M_ROWS * DIM];   // V transposed: [b][hd][token]
__device__ __half g_a [M_ROWS * DIM];
__device__ __half g_x [M_ROWS * DIM];
__device__ __half g_wq[DIM * DIM];
__device__ __half g_wv[DIM * DIM];
__device__ __half g_wo[DIM * DIM];
__device__ float  g_sq[64 * 1024];      // |q|^2 * 0.125 * log2(e)

#define C2EXP 0.36067376022224085f      // 2 * 0.125 * log2(e)

__device__ __forceinline__ float ex2(float x) {
    float r;
    asm("ex2.approx.f32 %0, %1;" : "=f"(r) : "f"(x));
    return r;
}
__device__ __forceinline__ uint32_t ldh2(const __half* p) {
    return *(const uint32_t*)p;
}
__device__ __forceinline__ uint32_t packh2(float lo, float hi) {
    __half2 h = __floats2half2_rn(lo, hi);
    return *(uint32_t*)&h;
}

// D += A(16x16) * B(16x8), fp16 inputs, fp32 accum
__device__ __forceinline__ void mma_f16(float c[4],
                                        uint32_t a0, uint32_t a1,
                                        uint32_t a2, uint32_t a3,
                                        uint32_t b0, uint32_t b1) {
    asm volatile(
        "mma.sync.aligned.m16n8k16.row.col.f32.f16.f16.f32 "
        "{%0,%1,%2,%3}, {%4,%5,%6,%7}, {%8,%9}, {%0,%1,%2,%3};\n"
        : "+f"(c[0]), "+f"(c[1]), "+f"(c[2]), "+f"(c[3])
        : "r"(a0), "r"(a1), "r"(a2), "r"(a3), "r"(b0), "r"(b1));
}

__device__ __forceinline__ void cp16(uint32_t smem_u32, const void* gptr) {
    asm volatile("cp.async.cg.shared.global [%0], [%1], 16;\n"
                 :: "r"(smem_u32), "l"(gptr));
}
#define CP_COMMIT() asm volatile("cp.async.commit_group;\n" ::: "memory")

// ---------------------------------------------------------------------------
// fp32 -> fp16 conversion: x (4M elems) + Wq/Wv/Wo (1M each)
// ---------------------------------------------------------------------------
__global__ __launch_bounds__(256) void conv_kernel(
    const float4* __restrict__ x,  __half* __restrict__ xo,
    const float4* __restrict__ w0, __half* __restrict__ w0o,
    const float4* __restrict__ w1, __half* __restrict__ w1o,
    const float4* __restrict__ w2, __half* __restrict__ w2o)
{
    int i = blockIdx.x * 256 + threadIdx.x;    // 8-elem units; grid covers 524288
    {
        float4 a = x[2 * i], b = x[2 * i + 1];
        uint4 u = { packh2(a.x, a.y), packh2(a.z, a.w),
                    packh2(b.x, b.y), packh2(b.z, b.w) };
        *(uint4*)(xo + 8 * (size_t)i) = u;
    }
    if (i < 131072) {
        float4 a = w0[2 * i], b = w0[2 * i + 1];
        uint4 u = { packh2(a.x, a.y), packh2(a.z, a.w),
                    packh2(b.x, b.y), packh2(b.z, b.w) };
        *(uint4*)(w0o + 8 * (size_t)i) = u;
        a = w1[2 * i]; b = w1[2 * i + 1];
        uint4 v = { packh2(a.x, a.y), packh2(a.z, a.w),
                    packh2(b.x, b.y), packh2(b.z, b.w) };
        *(uint4*)(w1o + 8 * (size_t)i) = v;
        a = w2[2 * i]; b = w2[2 * i + 1];
        uint4 w = { packh2(a.x, a.y), packh2(a.z, a.w),
                    packh2(b.x, b.y), packh2(b.z, b.w) };
        *(uint4*)(w2o + 8 * (size_t)i) = w;
    }
}

// ---------------------------------------------------------------------------
// scaled |q|^2 table from half q
// ---------------------------------------------------------------------------
__global__ __launch_bounds__(256) void sq_kernel(
    const __half* __restrict__ q, float* __restrict__ sqg)
{
    int o  = blockIdx.x * 256 + threadIdx.x;
    int n  = o & 1023;
    int bh = o >> 10;
    int b  = bh >> 4, h = bh & 15;
    const uint4* p = (const uint4*)(q + ((size_t)(b * 1024 + n)) * DIM + h * 64);
    float s = 0.f;
#pragma unroll
    for (int i = 0; i < 8; i++) {
        uint4 u = p[i];
        float2 f0 = __half22float2(*(__half2*)&u.x);
        float2 f1 = __half22float2(*(__half2*)&u.y);
        float2 f2 = __half22float2(*(__half2*)&u.z);
        float2 f3 = __half22float2(*(__half2*)&u.w);
        s += f0.x * f0.x + f0.y * f0.y + f1.x * f1.x + f1.y * f1.y
           + f2.x * f2.x + f2.y * f2.y + f3.x * f3.x + f3.y * f3.y;
    }
    sqg[o] = s * (0.5f * C2EXP);
}

// ---------------------------------------------------------------------------
// fp16 GEMM: C[M,N] = A[M,K] @ B[N,K]^T + bias (torch Linear), fp32 accum.
// 256 thr, 8 warps (4M x 2N), tile 128x128, K-step 64, 2-stage cp.async.
// mode: 0 = fp32 out, 1 = fp16 out, 2 = fp16 out TRANSPOSED (for V^T).
// blockIdx.z selects (B,bias,C,mode) pair -> fused Q/V projection.
// ---------------------------------------------------------------------------
#define SH 72                          // smem row stride in halves
#define G_STAGE_H (2 * 128 * SH)       // halves per stage (A+B tiles)
#define GEMM_SMEM (2 * G_STAGE_H * 2)  // 73728 bytes

__device__ __forceinline__ void g_load(
    uint32_t sb, int st, const __half* __restrict__ A,
    const __half* __restrict__ B, int bm, int bn, int k0, int t)
{
    uint32_t ab = sb + st * G_STAGE_H * 2;
    uint32_t bb = ab + 128 * SH * 2;
#pragma unroll
    for (int l = 0; l < 4; l++) {
        int idx = t + l * 256;
        int r = idx >> 3, c = (idx & 7) * 8;
        cp16(ab + (r * SH + c) * 2, A + (size_t)(bm + r) * DIM + k0 + c);
    }
#pragma unroll
    for (int l = 0; l < 4; l++) {
        int idx = t + l * 256;
        int r = idx >> 3, c = (idx & 7) * 8;
        cp16(bb + (r * SH + c) * 2, B + (size_t)(bn + r) * DIM + k0 + c);
    }
    CP_COMMIT();
}

__global__ __launch_bounds__(256, 2) void gemm_f16_kernel(
    const __half* __restrict__ A,
    const __half* __restrict__ B0, const float* __restrict__ bias0,
    void* C0, int mode0,
    const __half* __restrict__ B1, const float* __restrict__ bias1,
    void* C1, int mode1)
{
    extern __shared__ __half smh[];
    const uint32_t sb = (uint32_t)__cvta_generic_to_shared(smh);

    const __half* B    = blockIdx.z ? B1 : B0;
    const float*  bias = blockIdx.z ? bias1 : bias0;
    void*         C    = blockIdx.z ? C1 : C0;
    const int     mode = blockIdx.z ? mode1 : mode0;

    const int t    = threadIdx.x;
    const int w    = t >> 5;
    const int lane = t & 31;
    const int g    = lane >> 2;
    const int tq   = lane & 3;
    const int wm   = w & 3;
    const int wn   = w >> 2;
    const int bm   = blockIdx.y * 128;
    const int bn   = blockIdx.x * 128;

    float acc[2][8][4];
#pragma unroll
    for (int i = 0; i < 2; i++)
#pragma unroll
        for (int j = 0; j < 8; j++)
#pragma unroll
            for (int r = 0; r < 4; r++) acc[i][j][r] = 0.f;

    g_load(sb, 0, A, B, bm, bn, 0, t);

    for (int it = 0; it < 16; it++) {
        const int cur = it & 1;
        asm volatile("cp.async.wait_group 0;\n" ::: "memory");
        __syncthreads();
        if (it + 1 < 16)
            g_load(sb, cur ^ 1, A, B, bm, bn, (it + 1) * 64, t);

        const __half* As = smh + cur * G_STAGE_H;
        const __half* Bs = As + 128 * SH;

#pragma unroll
        for (int ks = 0; ks < 4; ks++) {
            const int kk = ks * 16;
            uint32_t a[2][4], b[8][2];
#pragma unroll
            for (int i = 0; i < 2; i++) {
                const __half* ar = As + (wm * 32 + i * 16 + g) * SH + kk + 2 * tq;
                a[i][0] = ldh2(ar);
                a[i][1] = ldh2(ar + 8 * SH);
                a[i][2] = ldh2(ar + 8);
                a[i][3] = ldh2(ar + 8 * SH + 8);
            }
#pragma unroll
            for (int j = 0; j < 8; j++) {
                const __half* br = Bs + (wn * 64 + j * 8 + g) * SH + kk + 2 * tq;
                b[j][0] = ldh2(br);
                b[j][1] = ldh2(br + 8);
            }
#pragma unroll
            for (int i = 0; i < 2; i++)
#pragma unroll
                for (int j = 0; j < 8; j++)
                    mma_f16(acc[i][j], a[i][0], a[i][1], a[i][2], a[i][3],
                            b[j][0], b[j][1]);
        }
    }

    if (mode == 0) {
        float* Cf = (float*)C;
#pragma unroll
        for (int i = 0; i < 2; i++) {
            int row0 = bm + wm * 32 + i * 16 + g;
#pragma unroll
            for (int j = 0; j < 8; j++) {
                int col0 = bn + wn * 64 + j * 8 + 2 * tq;
                float b0 = bias[col0], b1 = bias[col0 + 1];
                *(float2*)(Cf + (size_t)row0 * DIM + col0) =
                    make_float2(acc[i][j][0] + b0, acc[i][j][1] + b1);
                *(float2*)(Cf + (size_t)(row0 + 8) * DIM + col0) =
                    make_float2(acc[i][j][2] + b0, acc[i][j][3] + b1);
            }
        }
    } else if (mode == 1) {
        __half* Ch = (__half*)C;
#pragma unroll
        for (int i = 0; i < 2; i++) {
            int row0 = bm + wm * 32 + i * 16 + g;
#pragma unroll
            for (int j = 0; j < 8; j++) {
                int col0 = bn + wn * 64 + j * 8 + 2 * tq;
                float b0 = bias[col0], b1 = bias[col0 + 1];
                *(uint32_t*)(Ch + (size_t)row0 * DIM + col0) =
                    packh2(acc[i][j][0] + b0, acc[i][j][1] + b1);
                *(uint32_t*)(Ch + (size_t)(row0 + 8) * DIM + col0) =
                    packh2(acc[i][j][2] + b0, acc[i][j][3] + b1);
            }
        }
    } else {
        // transposed epilogue via smem: write C^T tile to g_vt[b][hd][token]
        __syncthreads();           // stage smem fully consumed -> reuse as T
        __half* T = smh;           // [128 cols][128 rows], stride 136
#pragma unroll
        for (int i = 0; i < 2; i++) {
            int rl = wm * 32 + i * 16 + g;
#pragma unroll
            for (int j = 0; j < 8; j++) {
                int cl = wn * 64 + j * 8 + 2 * tq;
                float b0 = bias[bn + cl], b1 = bias[bn + cl + 1];
                T[cl * 136 + rl]           = __float2half_rn(acc[i][j][0] + b0);
                T[(cl + 1) * 136 + rl]     = __float2half_rn(acc[i][j][1] + b1);
                T[cl * 136 + rl + 8]       = __float2half_rn(acc[i][j][2] + b0);
                T[(cl + 1) * 136 + rl + 8] = __float2half_rn(acc[i][j][3] + b1);
            }
        }
        __syncthreads();
        __half* Ch = (__half*)C;
        const int b    = bm >> 10;
        const int tokb = bm & 1023;
#pragma unroll
        for (int l = 0; l < 8; l++) {
            int idx = t + l * 256;
            int r = idx >> 4, c = (idx & 15) * 8;
            uint4 u = *(const uint4*)(T + r * 136 + c);
            *(uint4*)(Ch + ((size_t)(b * 1024 + bn + r)) * 1024 + tokb + c) = u;
        }
    }
}

// ---------------------------------------------------------------------------
// Fused attention (fp16 MMA): 128-query tile, 8 warps x 16 rows, 2 CTAs/SM,
// 2-stage 64-key ring. K from q (row-major), V from g_vt (dim-major).
// p = exp2(qk*C2 - si' - sj'); scores <= ~0 -> softmax w/o running max.
// ---------------------------------------------------------------------------
#define KST (64 * SH)               // 4608 halves per K stage
#define VST (64 * SH)               // 4608 halves per Vt stage
#define OFF_K  0
#define OFF_V  (2 * KST)            // 9216
#define OFF_S  (OFF_V + 2 * VST)    // 18432 (S chunks; Q staged here first)
#define SQ_H   (OFF_S + 128 * SH)   // 27648 (half units; float table after)
#define ATT_BYTES (SQ_H * 2 + 4096) // 59392 B

__device__ __forceinline__ void a_load(
    uint32_t sb, int s, const __half* __restrict__ qb,
    const __half* __restrict__ vtb, int key0, int t)
{
#pragma unroll
    for (int l = 0; l < 2; l++) {
        int idx = t + l * 256;                 // 0..511
        int r = idx >> 3, c = (idx & 7) * 8;
        cp16(sb + (OFF_K + s * KST + r * SH + c) * 2,
             qb + (size_t)(key0 + r) * DIM + c);
    }
#pragma unroll
    for (int l = 0; l < 2; l++) {
        int idx = t + l * 256;
        int r = idx >> 3, c = (idx & 7) * 8;
        cp16(sb + (OFF_V + s * VST + r * SH + c) * 2,
             vtb + (size_t)r * 1024 + key0 + c);
    }
    CP_COMMIT();
}

__global__ __launch_bounds__(256, 2) void attn_f16_kernel(
    const __half* __restrict__ q, const __half* __restrict__ vt,
    const float* __restrict__ sqg, __half* __restrict__ o)
{
    extern __shared__ __half smh[];
    const uint32_t sb = (uint32_t)__cvta_generic_to_shared(smh);

    const int bh = blockIdx.y;
    const int b  = bh >> 4;
    const int h  = bh & 15;
    const int qt = blockIdx.x * 128;
    const int t    = threadIdx.x;
    const int w    = t >> 5;
    const int lane = t & 31;
    const int g    = lane >> 2;
    const int tq   = lane & 3;
    const int i0   = 16 * w;

    const __half* qbase  = q + ((size_t)b * 1024) * DIM + h * 64;
    const __half* vtbase = vt + ((size_t)(b * 1024 + h * 64)) * 1024;

    a_load(sb, 0, qbase, vtbase, 0, t);
    a_load(sb, 1, qbase, vtbase, 64, t);

    float* sqa = (float*)(smh + SQ_H);
    ((float4*)sqa)[t] = ((const float4*)(sqg + (size_t)bh * 1024))[t];

    // stage Q tile into S region (transient)
    __half* Qs = smh + OFF_S;
#pragma unroll
    for (int l = 0; l < 4; l++) {
        int idx = t + l * 256;
        int r = idx >> 3, c = (idx & 7) * 8;
        *(uint4*)(Qs + r * SH + c) =
            *(const uint4*)(qbase + (size_t)(qt + r) * DIM + c);
    }
    __syncthreads();

    uint32_t qa[4][4];
#pragma unroll
    for (int ks = 0; ks < 4; ks++) {
        const __half* qr = Qs + (i0 + g) * SH + ks * 16 + 2 * tq;
        qa[ks][0] = ldh2(qr);
        qa[ks][1] = ldh2(qr + 8 * SH);
        qa[ks][2] = ldh2(qr + 8);
        qa[ks][3] = ldh2(qr + 8 * SH + 8);
    }
    const float si_lo = sqa[qt + i0 + g];
    const float si_hi = sqa[qt + i0 + 8 + g];
    __syncthreads();   // Q staging consumed -> S reusable

    float oacc[8][4];
#pragma unroll
    for (int j = 0; j < 8; j++)
#pragma unroll
        for (int r = 0; r < 4; r++) oacc[j][r] = 0.f;
    float den_lo = 0.f, den_hi = 0.f;
    __half* Swb = smh + OFF_S + w * (16 * SH);

    for (int it = 0; it < 16; it++) {
        const int s = it & 1;
        if (it < 15)
            asm volatile("cp.async.wait_group 1;\n" ::: "memory");
        else
            asm volatile("cp.async.wait_group 0;\n" ::: "memory");
        __syncthreads();

        const __half* Ksc = smh + OFF_K + s * KST;
        const __half* Vsc = smh + OFF_V + s * VST;
        const float*  sqk = sqa + it * 64;

        float c[4][4];
#pragma unroll
        for (int jj = 0; jj < 4; jj++)
#pragma unroll
            for (int r = 0; r < 4; r++) c[jj][r] = 0.f;
#pragma unroll
        for (int ks = 0; ks < 4; ks++)
#pragma unroll
            for (int jj = 0; jj < 4; jj++) {
                const __half* kr = Ksc + (jj * 8 + g) * SH + ks * 16 + 2 * tq;
                mma_f16(c[jj], qa[ks][0], qa[ks][1], qa[ks][2], qa[ks][3],
                        ldh2(kr), ldh2(kr + 8));
            }

#pragma unroll
        for (int jc = 0; jc < 2; jc++) {
            const int par = jc * 32;

            // softmax(jc): exp2, round to half, store, accumulate denom
#pragma unroll
            for (int jj = 0; jj < 4; jj++) {
                int cb = jj * 8 + 2 * tq;
                float sj0 = sqk[par + cb], sj1 = sqk[par + cb + 1];
                float p00 = ex2(fmaf(c[jj][0], C2EXP, -si_lo - sj0));
                float p01 = ex2(fmaf(c[jj][1], C2EXP, -si_lo - sj1));
                float p10 = ex2(fmaf(c[jj][2], C2EXP, -si_hi - sj0));
                float p11 = ex2(fmaf(c[jj][3], C2EXP, -si_hi - sj1));
                __half2 hl = __floats2half2_rn(p00, p01);
                __half2 hh = __floats2half2_rn(p10, p11);
                float2 fl = __half22float2(hl);
                float2 fh = __half22float2(hh);
                den_lo += fl.x + fl.y;
                den_hi += fh.x + fh.y;
                *(__half2*)(Swb + g * SH + par + cb)       = hl;
                *(__half2*)(Swb + (g + 8) * SH + par + cb) = hh;
            }
            __syncwarp();

            // scores(jc+1) while tensor pipe drains
            if (jc < 1) {
#pragma unroll
                for (int jj = 0; jj < 4; jj++)
#pragma unroll
                    for (int r = 0; r < 4; r++) c[jj][r] = 0.f;
#pragma unroll
                for (int ks = 0; ks < 4; ks++)
#pragma unroll
                    for (int jj = 0; jj < 4; jj++) {
                        const __half* kr = Ksc + (32 + jj * 8 + g) * SH + ks * 16 + 2 * tq;
                        mma_f16(c[jj], qa[ks][0], qa[ks][1], qa[ks][2], qa[ks][3],
                                ldh2(kr), ldh2(kr + 8));
                    }
            }

            // PV(jc): A = P (warp-private S), B = Vt
#pragma unroll
            for (int ksl = 0; ksl < 2; ksl++) {
                const __half* sr = Swb + g * SH + par + ksl * 16 + 2 * tq;
                uint32_t a0 = ldh2(sr);
                uint32_t a1 = ldh2(sr + 8 * SH);
                uint32_t a2 = ldh2(sr + 8);
                uint32_t a3 = ldh2(sr + 8 * SH + 8);
#pragma unroll
                for (int j = 0; j < 8; j++) {
                    const __half* vr = Vsc + (j * 8 + g) * SH + par + ksl * 16 + 2 * tq;
                    mma_f16(oacc[j], a0, a1, a2, a3, ldh2(vr), ldh2(vr + 8));
                }
            }
        }
        __syncthreads();   // stage s consumed by all warps

        if (it + 2 < 16)
            a_load(sb, s, qbase, vtbase, (it + 2) * 64, t);
    }

    den_lo += __shfl_xor_sync(0xffffffffu, den_lo, 1);
    den_lo += __shfl_xor_sync(0xffffffffu, den_lo, 2);
    den_hi += __shfl_xor_sync(0xffffffffu, den_hi, 1);
    den_hi += __shfl_xor_sync(0xffffffffu, den_hi, 2);
    const float inv_lo = 1.f / den_lo;
    const float inv_hi = 1.f / den_hi;

    __half* orow_lo = o + (size_t)(b * 1024 + qt + i0 + g) * DIM + h * 64;
    __half* orow_hi = o + (size_t)(b * 1024 + qt + i0 + 8 + g) * DIM + h * 64;
#pragma unroll
    for (int j = 0; j < 8; j++) {
        int col = j * 8 + 2 * tq;
        *(uint32_t*)(orow_lo + col) = packh2(oacc[j][0] * inv_lo,
                                             oacc[j][1] * inv_lo);
        *(uint32_t*)(orow_hi + col) = packh2(oacc[j][2] * inv_hi,
                                             oacc[j][3] * inv_hi);
    }
}

// ---------------------------------------------------------------------------
extern "C" void kernel_launch(void* const* d_in, const int* in_sizes, int n_in,
                              void* d_out, int out_size)
{
    const float* x  = (const float*)d_in[0];
    const float* Wq = (const float*)d_in[1];
    const float* bq = (const float*)d_in[2];
    const float* Wv = (const float*)d_in[3];
    const float* bv = (const float*)d_in[4];
    const float* Wo = (const float*)d_in[5];
    const float* bo = (const float*)d_in[6];
    float* out = (float*)d_out;

    __half *qp, *vtp, *ap, *xp, *wqp, *wvp, *wop;
    float* sqp;
    cudaGetSymbolAddress((void**)&qp,  g_q);
    cudaGetSymbolAddress((void**)&vtp, g_vt);
    cudaGetSymbolAddress((void**)&ap,  g_a);
    cudaGetSymbolAddress((void**)&xp,  g_x);
    cudaGetSymbolAddress((void**)&wqp, g_wq);
    cudaGetSymbolAddress((void**)&wvp, g_wv);
    cudaGetSymbolAddress((void**)&wop, g_wo);
    cudaGetSymbolAddress((void**)&sqp, g_sq);

    cudaFuncSetAttribute(gemm_f16_kernel,
                         cudaFuncAttributeMaxDynamicSharedMemorySize, GEMM_SMEM);
    cudaFuncSetAttribute(attn_f16_kernel,
                         cudaFuncAttributeMaxDynamicSharedMemorySize, ATT_BYTES);

    conv_kernel<<<2048, 256>>>(
        (const float4*)x,  xp,
        (const float4*)Wq, wqp,
        (const float4*)Wv, wvp,
        (const float4*)Wo, wop);

    // fused Q (row-major half) + V (transposed half) projections
    gemm_f16_kernel<<<dim3(8, 32, 2), 256, GEMM_SMEM>>>(
        xp, wqp, bq, (void*)qp, 1, wvp, bv, (void*)vtp, 2);

    sq_kernel<<<256, 256>>>(qp, sqp);

    attn_f16_kernel<<<dim3(8, 64), 256, ATT_BYTES>>>(qp, vtp, sqp, ap);

    gemm_f16_kernel<<<dim3(8, 32, 1), 256, GEMM_SMEM>>>(
        ap, wop, bo, (void*)out, 0, wop, bo, (void*)out, 0);
}

// round 11
// speedup vs baseline: 1.9056x; 1.0668x over previous
#include <cuda_runtime.h>
#include <cuda_fp16.h>
#include <cstdint>

// ---------------------------------------------------------------------------
// L2Attention via fp16 mma.sync (m16n8k16, fp32 accumulate).
// Attention: P stays in registers between score-MMA and PV-MMA (FA2-style
// fragment forwarding) -> no smem round-trip for probabilities.
// b=4, n=1024, dim=1024, heads=16, d=64
// ---------------------------------------------------------------------------

#define M_ROWS 4096
#define DIM    1024

__device__ __half g_q [M_ROWS * DIM];
__device__ __half g_vt[M_ROWS * DIM];   // V transposed: [b][hd][token]
__device__ __half g_a [M_ROWS * DIM];
__device__ __half g_x [M_ROWS * DIM];
__device__ __half g_wq[DIM * DIM];
__device__ __half g_wv[DIM * DIM];
__device__ __half g_wo[DIM * DIM];
__device__ float  g_sq[64 * 1024];      // |q|^2 * 0.125 * log2(e)

#define C2EXP 0.36067376022224085f      // 2 * 0.125 * log2(e)

__device__ __forceinline__ float ex2(float x) {
    float r;
    asm("ex2.approx.f32 %0, %1;" : "=f"(r) : "f"(x));
    return r;
}
__device__ __forceinline__ uint32_t ldh2(const __half* p) {
    return *(const uint32_t*)p;
}
__device__ __forceinline__ uint32_t packh2(float lo, float hi) {
    __half2 h = __floats2half2_rn(lo, hi);
    return *(uint32_t*)&h;
}

// D += A(16x16) * B(16x8), fp16 inputs, fp32 accum
__device__ __forceinline__ void mma_f16(float c[4],
                                        uint32_t a0, uint32_t a1,
                                        uint32_t a2, uint32_t a3,
                                        uint32_t b0, uint32_t b1) {
    asm volatile(
        "mma.sync.aligned.m16n8k16.row.col.f32.f16.f16.f32 "
        "{%0,%1,%2,%3}, {%4,%5,%6,%7}, {%8,%9}, {%0,%1,%2,%3};\n"
        : "+f"(c[0]), "+f"(c[1]), "+f"(c[2]), "+f"(c[3])
        : "r"(a0), "r"(a1), "r"(a2), "r"(a3), "r"(b0), "r"(b1));
}

__device__ __forceinline__ void cp16(uint32_t smem_u32, const void* gptr) {
    asm volatile("cp.async.cg.shared.global [%0], [%1], 16;\n"
                 :: "r"(smem_u32), "l"(gptr));
}
#define CP_COMMIT() asm volatile("cp.async.commit_group;\n" ::: "memory")

// ---------------------------------------------------------------------------
// fp32 -> fp16 conversion: x (4M elems) + Wq/Wv/Wo (1M each)
// ---------------------------------------------------------------------------
__global__ __launch_bounds__(256) void conv_kernel(
    const float4* __restrict__ x,  __half* __restrict__ xo,
    const float4* __restrict__ w0, __half* __restrict__ w0o,
    const float4* __restrict__ w1, __half* __restrict__ w1o,
    const float4* __restrict__ w2, __half* __restrict__ w2o)
{
    int i = blockIdx.x * 256 + threadIdx.x;    // 8-elem units
    {
        float4 a = x[2 * i], b = x[2 * i + 1];
        uint4 u = { packh2(a.x, a.y), packh2(a.z, a.w),
                    packh2(b.x, b.y), packh2(b.z, b.w) };
        *(uint4*)(xo + 8 * (size_t)i) = u;
    }
    if (i < 131072) {
        float4 a = w0[2 * i], b = w0[2 * i + 1];
        uint4 u = { packh2(a.x, a.y), packh2(a.z, a.w),
                    packh2(b.x, b.y), packh2(b.z, b.w) };
        *(uint4*)(w0o + 8 * (size_t)i) = u;
        a = w1[2 * i]; b = w1[2 * i + 1];
        uint4 v = { packh2(a.x, a.y), packh2(a.z, a.w),
                    packh2(b.x, b.y), packh2(b.z, b.w) };
        *(uint4*)(w1o + 8 * (size_t)i) = v;
        a = w2[2 * i]; b = w2[2 * i + 1];
        uint4 w = { packh2(a.x, a.y), packh2(a.z, a.w),
                    packh2(b.x, b.y), packh2(b.z, b.w) };
        *(uint4*)(w2o + 8 * (size_t)i) = w;
    }
}

// ---------------------------------------------------------------------------
// scaled |q|^2 table from half q
// ---------------------------------------------------------------------------
__global__ __launch_bounds__(256) void sq_kernel(
    const __half* __restrict__ q, float* __restrict__ sqg)
{
    int o  = blockIdx.x * 256 + threadIdx.x;
    int n  = o & 1023;
    int bh = o >> 10;
    int b  = bh >> 4, h = bh & 15;
    const uint4* p = (const uint4*)(q + ((size_t)(b * 1024 + n)) * DIM + h * 64);
    float s = 0.f;
#pragma unroll
    for (int i = 0; i < 8; i++) {
        uint4 u = p[i];
        float2 f0 = __half22float2(*(__half2*)&u.x);
        float2 f1 = __half22float2(*(__half2*)&u.y);
        float2 f2 = __half22float2(*(__half2*)&u.z);
        float2 f3 = __half22float2(*(__half2*)&u.w);
        s += f0.x * f0.x + f0.y * f0.y + f1.x * f1.x + f1.y * f1.y
           + f2.x * f2.x + f2.y * f2.y + f3.x * f3.x + f3.y * f3.y;
    }
    sqg[o] = s * (0.5f * C2EXP);
}

// ---------------------------------------------------------------------------
// fp16 GEMM (unchanged from R10): C = A @ B^T + bias, fp32 accum.
// 256 thr, 8 warps (4M x 2N), tile 128x128, K-step 64, 2-stage cp.async.
// mode: 0 = fp32 out, 1 = fp16 out, 2 = fp16 out TRANSPOSED (for V^T).
// ---------------------------------------------------------------------------
#define SH 72                          // smem row stride in halves
#define G_STAGE_H (2 * 128 * SH)
#define GEMM_SMEM (2 * G_STAGE_H * 2)  // 73728 bytes

__device__ __forceinline__ void g_load(
    uint32_t sb, int st, const __half* __restrict__ A,
    const __half* __restrict__ B, int bm, int bn, int k0, int t)
{
    uint32_t ab = sb + st * G_STAGE_H * 2;
    uint32_t bb = ab + 128 * SH * 2;
#pragma unroll
    for (int l = 0; l < 4; l++) {
        int idx = t + l * 256;
        int r = idx >> 3, c = (idx & 7) * 8;
        cp16(ab + (r * SH + c) * 2, A + (size_t)(bm + r) * DIM + k0 + c);
    }
#pragma unroll
    for (int l = 0; l < 4; l++) {
        int idx = t + l * 256;
        int r = idx >> 3, c = (idx & 7) * 8;
        cp16(bb + (r * SH + c) * 2, B + (size_t)(bn + r) * DIM + k0 + c);
    }
    CP_COMMIT();
}

__global__ __launch_bounds__(256, 2) void gemm_f16_kernel(
    const __half* __restrict__ A,
    const __half* __restrict__ B0, const float* __restrict__ bias0,
    void* C0, int mode0,
    const __half* __restrict__ B1, const float* __restrict__ bias1,
    void* C1, int mode1)
{
    extern __shared__ __half smh[];
    const uint32_t sb = (uint32_t)__cvta_generic_to_shared(smh);

    const __half* B    = blockIdx.z ? B1 : B0;
    const float*  bias = blockIdx.z ? bias1 : bias0;
    void*         C    = blockIdx.z ? C1 : C0;
    const int     mode = blockIdx.z ? mode1 : mode0;

    const int t    = threadIdx.x;
    const int w    = t >> 5;
    const int lane = t & 31;
    const int g    = lane >> 2;
    const int tq   = lane & 3;
    const int wm   = w & 3;
    const int wn   = w >> 2;
    const int bm   = blockIdx.y * 128;
    const int bn   = blockIdx.x * 128;

    float acc[2][8][4];
#pragma unroll
    for (int i = 0; i < 2; i++)
#pragma unroll
        for (int j = 0; j < 8; j++)
#pragma unroll
            for (int r = 0; r < 4; r++) acc[i][j][r] = 0.f;

    g_load(sb, 0, A, B, bm, bn, 0, t);

    for (int it = 0; it < 16; it++) {
        const int cur = it & 1;
        asm volatile("cp.async.wait_group 0;\n" ::: "memory");
        __syncthreads();
        if (it + 1 < 16)
            g_load(sb, cur ^ 1, A, B, bm, bn, (it + 1) * 64, t);

        const __half* As = smh + cur * G_STAGE_H;
        const __half* Bs = As + 128 * SH;

#pragma unroll
        for (int ks = 0; ks < 4; ks++) {
            const int kk = ks * 16;
            uint32_t a[2][4], b[8][2];
#pragma unroll
            for (int i = 0; i < 2; i++) {
                const __half* ar = As + (wm * 32 + i * 16 + g) * SH + kk + 2 * tq;
                a[i][0] = ldh2(ar);
                a[i][1] = ldh2(ar + 8 * SH);
                a[i][2] = ldh2(ar + 8);
                a[i][3] = ldh2(ar + 8 * SH + 8);
            }
#pragma unroll
            for (int j = 0; j < 8; j++) {
                const __half* br = Bs + (wn * 64 + j * 8 + g) * SH + kk + 2 * tq;
                b[j][0] = ldh2(br);
                b[j][1] = ldh2(br + 8);
            }
#pragma unroll
            for (int i = 0; i < 2; i++)
#pragma unroll
                for (int j = 0; j < 8; j++)
                    mma_f16(acc[i][j], a[i][0], a[i][1], a[i][2], a[i][3],
                            b[j][0], b[j][1]);
        }
    }

    if (mode == 0) {
        float* Cf = (float*)C;
#pragma unroll
        for (int i = 0; i < 2; i++) {
            int row0 = bm + wm * 32 + i * 16 + g;
#pragma unroll
            for (int j = 0; j < 8; j++) {
                int col0 = bn + wn * 64 + j * 8 + 2 * tq;
                float b0 = bias[col0], b1 = bias[col0 + 1];
                *(float2*)(Cf + (size_t)row0 * DIM + col0) =
                    make_float2(acc[i][j][0] + b0, acc[i][j][1] + b1);
                *(float2*)(Cf + (size_t)(row0 + 8) * DIM + col0) =
                    make_float2(acc[i][j][2] + b0, acc[i][j][3] + b1);
            }
        }
    } else if (mode == 1) {
        __half* Ch = (__half*)C;
#pragma unroll
        for (int i = 0; i < 2; i++) {
            int row0 = bm + wm * 32 + i * 16 + g;
#pragma unroll
            for (int j = 0; j < 8; j++) {
                int col0 = bn + wn * 64 + j * 8 + 2 * tq;
                float b0 = bias[col0], b1 = bias[col0 + 1];
                *(uint32_t*)(Ch + (size_t)row0 * DIM + col0) =
                    packh2(acc[i][j][0] + b0, acc[i][j][1] + b1);
                *(uint32_t*)(Ch + (size_t)(row0 + 8) * DIM + col0) =
                    packh2(acc[i][j][2] + b0, acc[i][j][3] + b1);
            }
        }
    } else {
        // transposed epilogue via smem: write C^T tile to g_vt[b][hd][token]
        __syncthreads();
        __half* T = smh;           // [128 cols][128 rows], stride 136
#pragma unroll
        for (int i = 0; i < 2; i++) {
            int rl = wm * 32 + i * 16 + g;
#pragma unroll
            for (int j = 0; j < 8; j++) {
                int cl = wn * 64 + j * 8 + 2 * tq;
                float b0 = bias[bn + cl], b1 = bias[bn + cl + 1];
                T[cl * 136 + rl]           = __float2half_rn(acc[i][j][0] + b0);
                T[(cl + 1) * 136 + rl]     = __float2half_rn(acc[i][j][1] + b1);
                T[cl * 136 + rl + 8]       = __float2half_rn(acc[i][j][2] + b0);
                T[(cl + 1) * 136 + rl + 8] = __float2half_rn(acc[i][j][3] + b1);
            }
        }
        __syncthreads();
        __half* Ch = (__half*)C;
        const int b    = bm >> 10;
        const int tokb = bm & 1023;
#pragma unroll
        for (int l = 0; l < 8; l++) {
            int idx = t + l * 256;
            int r = idx >> 4, c = (idx & 15) * 8;
            uint4 u = *(const uint4*)(T + r * 136 + c);
            *(uint4*)(Ch + ((size_t)(b * 1024 + bn + r)) * 1024 + tokb + c) = u;
        }
    }
}

// ---------------------------------------------------------------------------
// Fused attention (fp16 MMA, register-resident P): 128-query tile,
// 8 warps x 16 rows, 2 CTAs/SM, 2-stage 64-key ring.
// Score accumulator fragments are rounded to half and fed DIRECTLY into the
// PV MMA as A-operands (layout identity of m16n8k16) -> no P smem traffic.
// p = exp2(qk*C2 - si' - sj'); scores <= ~0 -> softmax w/o running max.
// ---------------------------------------------------------------------------
#define KST (64 * SH)
#define VST (64 * SH)
#define OFF_K  0
#define OFF_V  (2 * KST)            // 9216
#define OFF_S  (OFF_V + 2 * VST)    // 18432: Q staging only (prologue)
#define SQ_H   (OFF_S + 128 * SH)   // 27648 halves; float table after
#define ATT_BYTES (SQ_H * 2 + 4096) // 59392 B

__device__ __forceinline__ void a_load(
    uint32_t sb, int s, const __half* __restrict__ qb,
    const __half* __restrict__ vtb, int key0, int t)
{
#pragma unroll
    for (int l = 0; l < 2; l++) {
        int idx = t + l * 256;
        int r = idx >> 3, c = (idx & 7) * 8;
        cp16(sb + (OFF_K + s * KST + r * SH + c) * 2,
             qb + (size_t)(key0 + r) * DIM + c);
    }
#pragma unroll
    for (int l = 0; l < 2; l++) {
        int idx = t + l * 256;
        int r = idx >> 3, c = (idx & 7) * 8;
        cp16(sb + (OFF_V + s * VST + r * SH + c) * 2,
             vtb + (size_t)r * 1024 + key0 + c);
    }
    CP_COMMIT();
}

__global__ __launch_bounds__(256, 2) void attn_f16_kernel(
    const __half* __restrict__ q, const __half* __restrict__ vt,
    const float* __restrict__ sqg, __half* __restrict__ o)
{
    extern __shared__ __half smh[];
    const uint32_t sb = (uint32_t)__cvta_generic_to_shared(smh);

    const int bh = blockIdx.y;
    const int b  = bh >> 4;
    const int h  = bh & 15;
    const int qt = blockIdx.x * 128;
    const int t    = threadIdx.x;
    const int w    = t >> 5;
    const int lane = t & 31;
    const int g    = lane >> 2;
    const int tq   = lane & 3;
    const int i0   = 16 * w;

    const __half* qbase  = q + ((size_t)b * 1024) * DIM + h * 64;
    const __half* vtbase = vt + ((size_t)(b * 1024 + h * 64)) * 1024;

    a_load(sb, 0, qbase, vtbase, 0, t);
    a_load(sb, 1, qbase, vtbase, 64, t);

    float* sqa = (float*)(smh + SQ_H);
    ((float4*)sqa)[t] = ((const float4*)(sqg + (size_t)bh * 1024))[t];

    // stage Q tile (transient; region unused afterwards)
    __half* Qs = smh + OFF_S;
#pragma unroll
    for (int l = 0; l < 4; l++) {
        int idx = t + l * 256;
        int r = idx >> 3, c = (idx & 7) * 8;
        *(uint4*)(Qs + r * SH + c) =
            *(const uint4*)(qbase + (size_t)(qt + r) * DIM + c);
    }
    __syncthreads();

    uint32_t qa[4][4];
#pragma unroll
    for (int ks = 0; ks < 4; ks++) {
        const __half* qr = Qs + (i0 + g) * SH + ks * 16 + 2 * tq;
        qa[ks][0] = ldh2(qr);
        qa[ks][1] = ldh2(qr + 8 * SH);
        qa[ks][2] = ldh2(qr + 8);
        qa[ks][3] = ldh2(qr + 8 * SH + 8);
    }
    const float nsi_lo = -sqa[qt + i0 + g];
    const float nsi_hi = -sqa[qt + i0 + 8 + g];
    __syncthreads();

    float oacc[8][4];
#pragma unroll
    for (int j = 0; j < 8; j++)
#pragma unroll
        for (int r = 0; r < 4; r++) oacc[j][r] = 0.f;
    float den_lo = 0.f, den_hi = 0.f;

    for (int it = 0; it < 16; it++) {
        const int s = it & 1;
        if (it < 15)
            asm volatile("cp.async.wait_group 1;\n" ::: "memory");
        else
            asm volatile("cp.async.wait_group 0;\n" ::: "memory");
        __syncthreads();

        const __half* Ksc = smh + OFF_K + s * KST;
        const __half* Vsc = smh + OFF_V + s * VST;
        const float*  sqk = sqa + it * 64;

        float c[4][4];
        uint32_t p[8];

        // ---- scores chunk 0 (keys 0..31) ----
#pragma unroll
        for (int jj = 0; jj < 4; jj++)
#pragma unroll
            for (int r = 0; r < 4; r++) c[jj][r] = 0.f;
#pragma unroll
        for (int ks = 0; ks < 4; ks++)
#pragma unroll
            for (int jj = 0; jj < 4; jj++) {
                const __half* kr = Ksc + (jj * 8 + g) * SH + ks * 16 + 2 * tq;
                mma_f16(c[jj], qa[ks][0], qa[ks][1], qa[ks][2], qa[ks][3],
                        ldh2(kr), ldh2(kr + 8));
            }

#pragma unroll
        for (int jc = 0; jc < 2; jc++) {
            const int par = jc * 32;

            // ---- softmax(jc): c -> p (register fragments) ----
#pragma unroll
            for (int jj = 0; jj < 4; jj++) {
                int cb = jj * 8 + 2 * tq;
                float2 sj = *(const float2*)(sqk + par + cb);
                float p00 = ex2(fmaf(c[jj][0], C2EXP, nsi_lo - sj.x));
                float p01 = ex2(fmaf(c[jj][1], C2EXP, nsi_lo - sj.y));
                float p10 = ex2(fmaf(c[jj][2], C2EXP, nsi_hi - sj.x));
                float p11 = ex2(fmaf(c[jj][3], C2EXP, nsi_hi - sj.y));
                uint32_t hl = packh2(p00, p01);
                uint32_t hh = packh2(p10, p11);
                float2 fl = __half22float2(*(__half2*)&hl);
                float2 fh = __half22float2(*(__half2*)&hh);
                den_lo += fl.x + fl.y;
                den_hi += fh.x + fh.y;
                p[2 * jj]     = hl;
                p[2 * jj + 1] = hh;
            }

            // ---- scores(jc+1) while tensor pipe drains ----
            if (jc < 1) {
#pragma unroll
                for (int jj = 0; jj < 4; jj++)
#pragma unroll
                    for (int r = 0; r < 4; r++) c[jj][r] = 0.f;
#pragma unroll
                for (int ks = 0; ks < 4; ks++)
#pragma unroll
                    for (int jj = 0; jj < 4; jj++) {
                        const __half* kr = Ksc + (32 + jj * 8 + g) * SH + ks * 16 + 2 * tq;
                        mma_f16(c[jj], qa[ks][0], qa[ks][1], qa[ks][2], qa[ks][3],
                                ldh2(kr), ldh2(kr + 8));
                    }
            }

            // ---- PV(jc): A = P fragments straight from registers ----
            //  keys [par+16k, par+16k+16):  a0=p[4k], a1=p[4k+1], a2=p[4k+2], a3=p[4k+3]
#pragma unroll
            for (int ksl = 0; ksl < 2; ksl++) {
                uint32_t a0 = p[4 * ksl + 0];
                uint32_t a1 = p[4 * ksl + 1];
                uint32_t a2 = p[4 * ksl + 2];
                uint32_t a3 = p[4 * ksl + 3];
#pragma unroll
                for (int j = 0; j < 8; j++) {
                    const __half* vr = Vsc + (j * 8 + g) * SH + par + ksl * 16 + 2 * tq;
                    mma_f16(oacc[j], a0, a1, a2, a3, ldh2(vr), ldh2(vr + 8));
                }
            }
        }
        __syncthreads();

        if (it + 2 < 16)
            a_load(sb, s, qbase, vtbase, (it + 2) * 64, t);
    }

    den_lo += __shfl_xor_sync(0xffffffffu, den_lo, 1);
    den_lo += __shfl_xor_sync(0xffffffffu, den_lo, 2);
    den_hi += __shfl_xor_sync(0xffffffffu, den_hi, 1);
    den_hi += __shfl_xor_sync(0xffffffffu, den_hi, 2);
    const float inv_lo = 1.f / den_lo;
    const float inv_hi = 1.f / den_hi;

    __half* orow_lo = o + (size_t)(b * 1024 + qt + i0 + g) * DIM + h * 64;
    __half* orow_hi = o + (size_t)(b * 1024 + qt + i0 + 8 + g) * DIM + h * 64;
#pragma unroll
    for (int j = 0; j < 8; j++) {
        int col = j * 8 + 2 * tq;
        *(uint32_t*)(orow_lo + col) = packh2(oacc[j][0] * inv_lo,
                                             oacc[j][1] * inv_lo);
        *(uint32_t*)(orow_hi + col) = packh2(oacc[j][2] * inv_hi,
                                             oacc[j][3] * inv_hi);
    }
}

// ---------------------------------------------------------------------------
extern "C" void kernel_launch(void* const* d_in, const int* in_sizes, int n_in,
                              void* d_out, int out_size)
{
    const float* x  = (const float*)d_in[0];
    const float* Wq = (const float*)d_in[1];
    const float* bq = (const float*)d_in[2];
    const float* Wv = (const float*)d_in[3];
    const float* bv = (const float*)d_in[4];
    const float* Wo = (const float*)d_in[5];
    const float* bo = (const float*)d_in[6];
    float* out = (float*)d_out;

    __half *qp, *vtp, *ap, *xp, *wqp, *wvp, *wop;
    float* sqp;
    cudaGetSymbolAddress((void**)&qp,  g_q);
    cudaGetSymbolAddress((void**)&vtp, g_vt);
    cudaGetSymbolAddress((void**)&ap,  g_a);
    cudaGetSymbolAddress((void**)&xp,  g_x);
    cudaGetSymbolAddress((void**)&wqp, g_wq);
    cudaGetSymbolAddress((void**)&wvp, g_wv);
    cudaGetSymbolAddress((void**)&wop, g_wo);
    cudaGetSymbolAddress((void**)&sqp, g_sq);

    cudaFuncSetAttribute(gemm_f16_kernel,
                         cudaFuncAttributeMaxDynamicSharedMemorySize, GEMM_SMEM);
    cudaFuncSetAttribute(attn_f16_kernel,
                         cudaFuncAttributeMaxDynamicSharedMemorySize, ATT_BYTES);

    conv_kernel<<<2048, 256>>>(
        (const float4*)x,  xp,
        (const float4*)Wq, wqp,
        (const float4*)Wv, wvp,
        (const float4*)Wo, wop);

    gemm_f16_kernel<<<dim3(8, 32, 2), 256, GEMM_SMEM>>>(
        xp, wqp, bq, (void*)qp, 1, wvp, bv, (void*)vtp, 2);

    sq_kernel<<<256, 256>>>(qp, sqp);

    attn_f16_kernel<<<dim3(8, 64), 256, ATT_BYTES>>>(qp, vtp, sqp, ap);

    gemm_f16_kernel<<<dim3(8, 32, 1), 256, GEMM_SMEM>>>(
        ap, wop, bo, (void*)out, 0, wop, bo, (void*)out, 0);
}